// round 13
// baseline (speedup 1.0000x reference)
#include <cuda_runtime.h>
#include <cuda_fp16.h>
#include <cstdint>
#include <math.h>

#define BATCH 4
#define CCH   512
#define NSP   4096
#define GROUPS 32
#define GSIZE  65536

static const long CN  = (long)CCH * NSP;
static const long NNL = (long)NSP * NSP;

// Scratch (device globals — allocation-free per harness rules)
__device__ __half g_ht[BATCH * CCH * NSP];  // normalized h transposed [B][N][C]
__device__ __half g_q [BATCH * CCH * NSP];  // q_t [B][N][C]
__device__ __half g_k [BATCH * CCH * NSP];  // k_t [B][N][C]
__device__ __half g_v [BATCH * CCH * NSP];  // v   [B][C][N]
__device__ __half g_o [BATCH * CCH * NSP];  // O_t [B][N][C]
__device__ __half g_p [BATCH * NSP * NSP];  // scores -> probs (in place, half)
__device__ __half g_w [4 * CCH * CCH];      // half wq,wk,wv,wp
__device__ float  g_mu [BATCH * GROUPS];
__device__ float  g_rsd[BATCH * GROUPS];

// ===========================================================================
// helpers
// ===========================================================================
__device__ __forceinline__ uint32_t s2u(const void* p) {
    uint32_t a;
    asm("{ .reg .u64 t; cvta.to.shared.u64 t, %1; cvt.u32.u64 %0, t; }"
        : "=r"(a) : "l"(p));
    return a;
}
__device__ __forceinline__ void cpa16(uint32_t d, const void* s) {
    asm volatile("cp.async.cg.shared.global [%0], [%1], 16;" :: "r"(d), "l"(s));
}
__device__ __forceinline__ void mma16(float* d, const uint32_t* a, const uint32_t* b) {
    asm volatile(
        "mma.sync.aligned.m16n8k16.row.col.f32.f16.f16.f32 "
        "{%0,%1,%2,%3}, {%4,%5,%6,%7}, {%8,%9}, {%0,%1,%2,%3};"
        : "+f"(d[0]), "+f"(d[1]), "+f"(d[2]), "+f"(d[3])
        : "r"(a[0]), "r"(a[1]), "r"(a[2]), "r"(a[3]), "r"(b[0]), "r"(b[1]));
}
__device__ __forceinline__ void ldm4(uint32_t* r, uint32_t addr) {
    asm volatile(
        "ldmatrix.sync.aligned.m8n8.x4.shared.b16 {%0,%1,%2,%3}, [%4];"
        : "=r"(r[0]), "=r"(r[1]), "=r"(r[2]), "=r"(r[3]) : "r"(addr));
}

// ===========================================================================
// GroupNorm stats: one block per (b, group); writes mu/rstd only.
// ===========================================================================
__global__ void gn_stats(const float* __restrict__ x,
                         float* __restrict__ mu_out,
                         float* __restrict__ rsd_out)
{
    const int bg  = blockIdx.x;
    const long base = (long)bg * GSIZE;
    const int tid = threadIdx.x;

    float s = 0.f, ss = 0.f;
    for (int i = tid * 4; i < GSIZE; i += 256 * 4) {
        float4 v = *(const float4*)(x + base + i);
        s  += v.x + v.y + v.z + v.w;
        ss += v.x*v.x + v.y*v.y + v.z*v.z + v.w*v.w;
    }
    __shared__ float rs[256], rq[256];
    rs[tid] = s; rq[tid] = ss;
    __syncthreads();
    for (int o = 128; o > 0; o >>= 1) {
        if (tid < o) { rs[tid] += rs[tid + o]; rq[tid] += rq[tid + o]; }
        __syncthreads();
    }
    if (tid == 0) {
        float mu  = rs[0] * (1.f / GSIZE);
        float var = rq[0] * (1.f / GSIZE) - mu * mu;
        mu_out[bg]  = mu;
        rsd_out[bg] = rsqrtf(var + 1e-6f);
    }
}

// ===========================================================================
// Fused normalize + transpose + fp16 convert: x[C,N] -> h_t[N,C] (half)
// ===========================================================================
__global__ void ntrans_kernel(const float* __restrict__ x,
                              const float* __restrict__ gamma,
                              const float* __restrict__ beta,
                              const float* __restrict__ mu,
                              const float* __restrict__ rsd,
                              __half* __restrict__ out)
{
    __shared__ float t[32][33];
    const int bz = blockIdx.z;
    const float* I = x + (long)bz * CN;
    __half* O = out + (long)bz * CN;
    const int c0 = blockIdx.y * 32, n0 = blockIdx.x * 32;
    const int tx = threadIdx.x, ty = threadIdx.y;   // (32, 8)
#pragma unroll
    for (int i = 0; i < 32; i += 8) {
        const int c = c0 + ty + i;
        const int bg = bz * GROUPS + (c >> 4);      // 16 channels per group
        const float ga = gamma[c] * rsd[bg];
        const float be = beta[c] - mu[bg] * ga;
        t[ty + i][tx] = I[(long)c * NSP + n0 + tx] * ga + be;
    }
    __syncthreads();
#pragma unroll
    for (int i = 0; i < 32; i += 8)
        O[(long)(n0 + ty + i) * CCH + c0 + tx] = __float2half_rn(t[tx][ty + i]);
}

// ===========================================================================
// fp32 -> fp16 convert: all 4 weight matrices in one launch (blockIdx.y picks)
// ===========================================================================
__global__ void tohalf4_kernel(const float* __restrict__ w0,
                               const float* __restrict__ w1,
                               const float* __restrict__ w2,
                               const float* __restrict__ w3,
                               __half* __restrict__ out, int n)
{
    const float* in = (blockIdx.y == 0) ? w0 : (blockIdx.y == 1) ? w1
                    : (blockIdx.y == 2) ? w2 : w3;
    __half* o = out + (long)blockIdx.y * n;
    int i = (blockIdx.x * 256 + threadIdx.x) * 4;
    if (i < n) {
        float4 v = *(const float4*)(in + i);
        *(__half2*)(o + i)     = __floats2half2_rn(v.x, v.y);
        *(__half2*)(o + i + 2) = __floats2half2_rn(v.z, v.w);
    }
}

// ===========================================================================
// fp16 tensor-core GEMM: mma.sync.m16n8k16 + ldmatrix + 2-stage cp.async.
//   D[m,n] = alpha * sum_k A[m*lda+k] * B[n*ldb+k] (+biasM[m]) (+biasN[n]) (+R)
// CTA tile 128x128, K-tile 64 halves (4 k16 steps), 4 warps (2x2),
// warp tile 64x64. smem row = 64 halves (128B) in 176B stride: rows start at
// word offsets 12r mod 32 -> every 8 rows tile all 32 banks; conflict-free
// ldmatrix; 16B aligned.
// Sync per K-tile: wait_group 0 -> __syncthreads -> issue next -> compute.
//  - wait+barrier makes stage kt's cp.async data visible to ALL threads.
//  - issuing stage (kt+1)&1 after the barrier is write-after-read safe
//    (readers from iteration kt-1 finished before the barrier).
// Dynamic smem: 2 stages * 256 rows * 176B = 90112 B; 2 CTAs/SM.
// ===========================================================================
#define TG_STRIDE  176u                // bytes per smem row
#define TG_B_OFF   22528u              // 128 rows * 176
#define TG_STAGE   45056u              // 256 rows * 176
#define TG_SMEM_BYTES 90112

template<bool HALF_C>
__global__ void __launch_bounds__(128, 2)
hgemm(const __half* __restrict__ A, const __half* __restrict__ B,
      void* __restrict__ Cv, int lda, int ldb, int ldc,
      long sA, long sB, long sC, long sR,
      int K, float alpha,
      const float* __restrict__ biasM, const float* __restrict__ biasN,
      const float* __restrict__ res)
{
    extern __shared__ __half sm[];
    const uint32_t sbase = s2u(sm);

    const int tid  = threadIdx.x;
    const int lane = tid & 31, wid = tid >> 5;
    const int m0 = blockIdx.y * 128, n0 = blockIdx.x * 128, bz = blockIdx.z;

    const __half* Ab = A + bz * sA + (long)m0 * lda;
    const __half* Bb = B + bz * sB + (long)n0 * ldb;

    // cp.async staging: thread t covers rows (t>>3)+16i (i=0..7), chunk t&7.
    const int r0 = tid >> 3;            // 0..15
    const int c16 = tid & 7;            // 16B chunk within the 128B row
    const uint32_t stDst = (uint32_t)r0 * TG_STRIDE + (uint32_t)c16 * 16u;
    const __half* pA = Ab + (long)r0 * lda + c16 * 8;
    const __half* pB = Bb + (long)r0 * ldb + c16 * 8;
    const long aS = (long)16 * lda;     // +16 rows
    const long bS = (long)16 * ldb;

    // warp/fragment addressing: warp grid 2x2, warp tile 64x64
    const int qid = lane >> 2, rid = lane & 3;
    const int mw = (wid >> 1) * 64, nw = (wid & 1) * 64;
    const uint32_t aLD = sbase + (uint32_t)(mw + (lane & 15)) * TG_STRIDE
                       + (uint32_t)((lane >> 4) & 1) * 16u;
    const uint32_t bLD = sbase + TG_B_OFF
        + (uint32_t)(nw + (lane & 7) + ((lane >> 4) & 1) * 8) * TG_STRIDE
        + (uint32_t)((lane >> 3) & 1) * 16u;

    float d[4][8][4];
#pragma unroll
    for (int i = 0; i < 4; i++)
#pragma unroll
        for (int j = 0; j < 8; j++)
#pragma unroll
            for (int l = 0; l < 4; l++) d[i][j][l] = 0.f;

    const int NK = K >> 6;              // K-tile = 64 halves

    // prologue: stage 0
    {
        const uint32_t ao = sbase + stDst;
#pragma unroll
        for (int i = 0; i < 8; i++) {
            cpa16(ao + (uint32_t)i * (16u * TG_STRIDE),            pA + i * aS);
            cpa16(ao + TG_B_OFF + (uint32_t)i * (16u * TG_STRIDE), pB + i * bS);
        }
        asm volatile("cp.async.commit_group;" ::: "memory");
    }

#pragma unroll 1
    for (int kt = 0; kt < NK; kt++) {
        const uint32_t bufo = (uint32_t)(kt & 1) * TG_STAGE;

        // 1) drain my stage-kt group, 2) barrier => data visible to all,
        //    and all reads of the other stage (iter kt-1) are complete.
        asm volatile("cp.async.wait_group 0;" ::: "memory");
        __syncthreads();

        // 3) prefetch kt+1 into the other stage (in flight during compute)
        if (kt + 1 < NK) {
            const uint32_t ao = sbase + ((uint32_t)((kt + 1) & 1) * TG_STAGE)
                              + stDst;
            const __half* qa = pA + (kt + 1) * 64;
            const __half* qb = pB + (kt + 1) * 64;
#pragma unroll
            for (int i = 0; i < 8; i++) {
                cpa16(ao + (uint32_t)i * (16u * TG_STRIDE),            qa + i * aS);
                cpa16(ao + TG_B_OFF + (uint32_t)i * (16u * TG_STRIDE), qb + i * bS);
            }
            asm volatile("cp.async.commit_group;" ::: "memory");
        }

        // 4) compute: 4 k-steps, fragments double-buffered
        uint32_t af[2][4][4], bf[2][4][4];
#pragma unroll
        for (int mi = 0; mi < 4; mi++)
            ldm4(af[0][mi], aLD + bufo + (uint32_t)mi * (16u * TG_STRIDE));
#pragma unroll
        for (int nj = 0; nj < 4; nj++)
            ldm4(bf[0][nj], bLD + bufo + (uint32_t)nj * (16u * TG_STRIDE));

#pragma unroll
        for (int ks = 0; ks < 4; ks++) {
            const int cur = ks & 1, nxt = cur ^ 1;
            if (ks < 3) {
                const uint32_t ko = (uint32_t)(ks + 1) * 32u;
#pragma unroll
                for (int mi = 0; mi < 4; mi++)
                    ldm4(af[nxt][mi], aLD + bufo + ko
                                      + (uint32_t)mi * (16u * TG_STRIDE));
#pragma unroll
                for (int nj = 0; nj < 4; nj++)
                    ldm4(bf[nxt][nj], bLD + bufo + ko
                                      + (uint32_t)nj * (16u * TG_STRIDE));
            }
#pragma unroll
            for (int mi = 0; mi < 4; mi++)
#pragma unroll
                for (int ni = 0; ni < 8; ni++)
                    mma16(d[mi][ni], af[cur][mi],
                          &bf[cur][ni >> 1][(ni & 1) * 2]);
        }
    }

    // epilogue
    const float* Rb = res ? (res + bz * sR) : nullptr;
#pragma unroll
    for (int mi = 0; mi < 4; mi++) {
        const int rA = m0 + mw + mi * 16 + qid;
        const int rB = rA + 8;
        const float bmA = biasM ? biasM[rA] : 0.f;
        const float bmB = biasM ? biasM[rB] : 0.f;
#pragma unroll
        for (int ni = 0; ni < 8; ni++) {
            const int col = n0 + nw + ni * 8 + rid * 2;
            float bn0 = 0.f, bn1 = 0.f;
            if (biasN) { bn0 = biasN[col]; bn1 = biasN[col + 1]; }
            float2 v0, v1;
            v0.x = d[mi][ni][0] * alpha + bmA + bn0;
            v0.y = d[mi][ni][1] * alpha + bmA + bn1;
            v1.x = d[mi][ni][2] * alpha + bmB + bn0;
            v1.y = d[mi][ni][3] * alpha + bmB + bn1;
            const long o0 = (long)rA * ldc + col;
            const long o1 = (long)rB * ldc + col;
            if (HALF_C) {
                __half* Ch = (__half*)Cv + bz * sC;
                *(__half2*)(Ch + o0) = __floats2half2_rn(v0.x, v0.y);
                *(__half2*)(Ch + o1) = __floats2half2_rn(v1.x, v1.y);
            } else {
                float* Cf = (float*)Cv + bz * sC;
                if (Rb) {
                    float2 ra = *(const float2*)(Rb + o0);
                    float2 rb = *(const float2*)(Rb + o1);
                    v0.x += ra.x; v0.y += ra.y;
                    v1.x += rb.x; v1.y += rb.y;
                }
                *(float2*)(Cf + o0) = v0;
                *(float2*)(Cf + o1) = v1;
            }
        }
    }
}

// ===========================================================================
// In-place register softmax over 4096 half scores -> half probs.
// ===========================================================================
__global__ void softmax_kernel(__half* __restrict__ s)
{
    const long row = blockIdx.x;
    __half* p = s + row * (long)NSP;
    const int tid = threadIdx.x;
    const int lane = tid & 31, wrp = tid >> 5;

    __shared__ float red[8];

    float v[16];
#pragma unroll
    for (int c = 0; c < 2; c++) {
        int4 pk = *(const int4*)(p + (tid + c * 256) * 8);
        const __half2* h2 = (const __half2*)&pk;
#pragma unroll
        for (int j = 0; j < 4; j++) {
            float2 f = __half22float2(h2[j]);
            v[c * 8 + j * 2]     = f.x;
            v[c * 8 + j * 2 + 1] = f.y;
        }
    }

    float m = v[0];
#pragma unroll
    for (int k = 1; k < 16; k++) m = fmaxf(m, v[k]);
#pragma unroll
    for (int o = 16; o > 0; o >>= 1)
        m = fmaxf(m, __shfl_xor_sync(0xffffffffu, m, o));
    if (lane == 0) red[wrp] = m;
    __syncthreads();
    m = red[lane & 7];
#pragma unroll
    for (int o = 4; o > 0; o >>= 1)
        m = fmaxf(m, __shfl_xor_sync(0xffffffffu, m, o));

    float sum = 0.f;
#pragma unroll
    for (int k = 0; k < 16; k++) {
        v[k] = __expf(v[k] - m);
        sum += v[k];
    }
#pragma unroll
    for (int o = 16; o > 0; o >>= 1)
        sum += __shfl_xor_sync(0xffffffffu, sum, o);
    __syncthreads();
    if (lane == 0) red[wrp] = sum;
    __syncthreads();
    sum = red[lane & 7];
#pragma unroll
    for (int o = 4; o > 0; o >>= 1)
        sum += __shfl_xor_sync(0xffffffffu, sum, o);
    const float inv = 1.f / sum;

#pragma unroll
    for (int c = 0; c < 2; c++) {
        int4 pk;
        __half2* h2 = (__half2*)&pk;
#pragma unroll
        for (int j = 0; j < 4; j++)
            h2[j] = __floats2half2_rn(v[c * 8 + j * 2] * inv,
                                      v[c * 8 + j * 2 + 1] * inv);
        *(int4*)(p + (tid + c * 256) * 8) = pk;
    }
}

// ===========================================================================
extern "C" void kernel_launch(void* const* d_in, const int* in_sizes, int n_in,
                              void* d_out, int out_size)
{
    const float* x     = (const float*)d_in[0];
    const float* gamma = (const float*)d_in[1];
    const float* beta  = (const float*)d_in[2];
    const float* wq    = (const float*)d_in[3];
    const float* bq    = (const float*)d_in[4];
    const float* wk    = (const float*)d_in[5];
    const float* bk    = (const float*)d_in[6];
    const float* wv    = (const float*)d_in[7];
    const float* bv    = (const float*)d_in[8];
    const float* wp    = (const float*)d_in[9];
    const float* bp    = (const float*)d_in[10];
    float* out = (float*)d_out;

    __half *pht, *pq, *pk, *pv, *po, *pp, *pw;
    float *pmu, *prs;
    cudaGetSymbolAddress((void**)&pht, g_ht);
    cudaGetSymbolAddress((void**)&pq,  g_q);
    cudaGetSymbolAddress((void**)&pk,  g_k);
    cudaGetSymbolAddress((void**)&pv,  g_v);
    cudaGetSymbolAddress((void**)&po,  g_o);
    cudaGetSymbolAddress((void**)&pp,  g_p);
    cudaGetSymbolAddress((void**)&pw,  g_w);
    cudaGetSymbolAddress((void**)&pmu, g_mu);
    cudaGetSymbolAddress((void**)&prs, g_rsd);

    cudaFuncSetAttribute(hgemm<true>,  cudaFuncAttributeMaxDynamicSharedMemorySize,
                         TG_SMEM_BYTES);
    cudaFuncSetAttribute(hgemm<false>, cudaFuncAttributeMaxDynamicSharedMemorySize,
                         TG_SMEM_BYTES);

    const int WN = CCH * CCH;           // 262144
    __half* rwq = pw;
    __half* rwk = pw + WN;
    __half* rwv = pw + 2 * WN;
    __half* rwp = pw + 3 * WN;

    // 0) convert the 4 weight matrices to fp16 (one launch)
    tohalf4_kernel<<<dim3(WN / 1024, 4), 256>>>(wq, wk, wv, wp, pw, WN);

    // 1) GroupNorm stats
    gn_stats<<<BATCH * GROUPS, 256>>>(x, pmu, prs);

    // 2) fused normalize + transpose -> h_t [N,C] (half)
    dim3 gT(NSP / 32, CCH / 32, BATCH);
    ntrans_kernel<<<gT, dim3(32, 8)>>>(x, gamma, beta, pmu, prs, pht);

    // 3) q_t[i,o] = sum_c h_t[i,c] wq[o,c] + bq[o]   (M=NSP, N=CCH)
    dim3 gNC(CCH / 128, NSP / 128, BATCH);   // (4, 32, 4)
    hgemm<true><<<gNC, 128, TG_SMEM_BYTES>>>(pht, rwq, pq, CCH, CCH, CCH,
                                             CN, 0, CN, 0,
                                             CCH, 1.f, nullptr, bq, nullptr);
    hgemm<true><<<gNC, 128, TG_SMEM_BYTES>>>(pht, rwk, pk, CCH, CCH, CCH,
                                             CN, 0, CN, 0,
                                             CCH, 1.f, nullptr, bk, nullptr);

    // 4) v[c,j] = sum_c' wv[c,c'] h_t[j,c'] + bv[c]  (M=CCH, N=NSP)
    dim3 gCN(NSP / 128, CCH / 128, BATCH);   // (32, 4, 4)
    hgemm<true><<<gCN, 128, TG_SMEM_BYTES>>>(rwv, pht, pv, CCH, CCH, NSP,
                                             0, CN, CN, 0,
                                             CCH, 1.f, bv, nullptr, nullptr);

    // 5) scores S[i,j] = scale * sum_c q_t[i,c] k_t[j,c] -> half, into g_p
    const float scale = 0.04419417382415922f;  // 512^-0.5
    dim3 gSS(NSP / 128, NSP / 128, BATCH);   // (32, 32, 4)
    hgemm<true><<<gSS, 128, TG_SMEM_BYTES>>>(pq, pk, pp, CCH, CCH, NSP,
                                             CN, CN, NNL, 0,
                                             CCH, scale, nullptr, nullptr, nullptr);

    // 6) in-place softmax over keys (half -> half)
    softmax_kernel<<<BATCH * NSP, 256>>>(pp);

    // 7) O_t[i,c] = sum_j P[i,j] v[c,j]   (M=NSP, N=CCH, K=NSP)
    hgemm<true><<<gNC, 128, TG_SMEM_BYTES>>>(pp, pv, po, NSP, NSP, CCH,
                                             NNL, CN, CN, 0,
                                             NSP, 1.f, nullptr, nullptr, nullptr);

    // 8) out[o,n] = sum_c wp[o,c] O_t[n,c] + bp[o] + x[o,n]  (M=CCH, N=NSP)
    hgemm<false><<<gCN, 128, TG_SMEM_BYTES>>>(rwp, po, out, CCH, CCH, NSP,
                                              0, CN, CN, CN,
                                              CCH, 1.f, bp, nullptr, x);
}

// round 14
// speedup vs baseline: 1.1155x; 1.1155x over previous
#include <cuda_runtime.h>
#include <cuda_fp16.h>
#include <cstdint>
#include <math.h>

#define BATCH 4
#define CCH   512
#define NSP   4096
#define GROUPS 32
#define GSIZE  65536

static const long CN  = (long)CCH * NSP;
static const long NNL = (long)NSP * NSP;
static const long QKS = (long)NSP * 1024;   // per-batch stride of merged q|k

// Scratch (device globals — allocation-free per harness rules)
__device__ __half g_ht[BATCH * CCH * NSP];   // normalized h transposed [B][N][C]
__device__ __half g_qk[BATCH * NSP * 1024];  // q|k merged [B][N][2C]
__device__ __half g_v [BATCH * CCH * NSP];   // v   [B][C][N]
__device__ __half g_o [BATCH * CCH * NSP];   // O_t [B][N][C]
__device__ __half g_p [BATCH * NSP * NSP];   // scores -> probs (in place, half)
__device__ __half g_w [4 * CCH * CCH];       // half wq,wk,wv,wp (wq,wk adjacent)
__device__ float  g_bqk[1024];               // concat bq|bk
__device__ float  g_mu [BATCH * GROUPS];
__device__ float  g_rsd[BATCH * GROUPS];

// ===========================================================================
// helpers
// ===========================================================================
__device__ __forceinline__ uint32_t s2u(const void* p) {
    uint32_t a;
    asm("{ .reg .u64 t; cvta.to.shared.u64 t, %1; cvt.u32.u64 %0, t; }"
        : "=r"(a) : "l"(p));
    return a;
}
__device__ __forceinline__ void cpa16(uint32_t d, const void* s) {
    asm volatile("cp.async.cg.shared.global [%0], [%1], 16;" :: "r"(d), "l"(s));
}
__device__ __forceinline__ void mma16(float* d, const uint32_t* a, const uint32_t* b) {
    asm volatile(
        "mma.sync.aligned.m16n8k16.row.col.f32.f16.f16.f32 "
        "{%0,%1,%2,%3}, {%4,%5,%6,%7}, {%8,%9}, {%0,%1,%2,%3};"
        : "+f"(d[0]), "+f"(d[1]), "+f"(d[2]), "+f"(d[3])
        : "r"(a[0]), "r"(a[1]), "r"(a[2]), "r"(a[3]), "r"(b[0]), "r"(b[1]));
}
__device__ __forceinline__ void ldm4(uint32_t* r, uint32_t addr) {
    asm volatile(
        "ldmatrix.sync.aligned.m8n8.x4.shared.b16 {%0,%1,%2,%3}, [%4];"
        : "=r"(r[0]), "=r"(r[1]), "=r"(r[2]), "=r"(r[3]) : "r"(addr));
}

// ===========================================================================
// GroupNorm stats: one block per (b, group); writes mu/rstd only.
// ===========================================================================
__global__ void gn_stats(const float* __restrict__ x,
                         float* __restrict__ mu_out,
                         float* __restrict__ rsd_out)
{
    const int bg  = blockIdx.x;
    const long base = (long)bg * GSIZE;
    const int tid = threadIdx.x;

    float s = 0.f, ss = 0.f;
    for (int i = tid * 4; i < GSIZE; i += 256 * 4) {
        float4 v = *(const float4*)(x + base + i);
        s  += v.x + v.y + v.z + v.w;
        ss += v.x*v.x + v.y*v.y + v.z*v.z + v.w*v.w;
    }
    __shared__ float rs[256], rq[256];
    rs[tid] = s; rq[tid] = ss;
    __syncthreads();
    for (int o = 128; o > 0; o >>= 1) {
        if (tid < o) { rs[tid] += rs[tid + o]; rq[tid] += rq[tid + o]; }
        __syncthreads();
    }
    if (tid == 0) {
        float mu  = rs[0] * (1.f / GSIZE);
        float var = rq[0] * (1.f / GSIZE) - mu * mu;
        mu_out[bg]  = mu;
        rsd_out[bg] = rsqrtf(var + 1e-6f);
    }
}

// ===========================================================================
// Fused normalize + transpose + fp16 convert: x[C,N] -> h_t[N,C] (half)
// ===========================================================================
__global__ void ntrans_kernel(const float* __restrict__ x,
                              const float* __restrict__ gamma,
                              const float* __restrict__ beta,
                              const float* __restrict__ mu,
                              const float* __restrict__ rsd,
                              __half* __restrict__ out)
{
    __shared__ float t[32][33];
    const int bz = blockIdx.z;
    const float* I = x + (long)bz * CN;
    __half* O = out + (long)bz * CN;
    const int c0 = blockIdx.y * 32, n0 = blockIdx.x * 32;
    const int tx = threadIdx.x, ty = threadIdx.y;   // (32, 8)
#pragma unroll
    for (int i = 0; i < 32; i += 8) {
        const int c = c0 + ty + i;
        const int bg = bz * GROUPS + (c >> 4);      // 16 channels per group
        const float ga = gamma[c] * rsd[bg];
        const float be = beta[c] - mu[bg] * ga;
        t[ty + i][tx] = I[(long)c * NSP + n0 + tx] * ga + be;
    }
    __syncthreads();
#pragma unroll
    for (int i = 0; i < 32; i += 8)
        O[(long)(n0 + ty + i) * CCH + c0 + tx] = __float2half_rn(t[tx][ty + i]);
}

// ===========================================================================
// fp32 -> fp16 convert: all 4 weight matrices in one launch (blockIdx.y picks)
// ===========================================================================
__global__ void tohalf4_kernel(const float* __restrict__ w0,
                               const float* __restrict__ w1,
                               const float* __restrict__ w2,
                               const float* __restrict__ w3,
                               __half* __restrict__ out, int n)
{
    const float* in = (blockIdx.y == 0) ? w0 : (blockIdx.y == 1) ? w1
                    : (blockIdx.y == 2) ? w2 : w3;
    __half* o = out + (long)blockIdx.y * n;
    int i = (blockIdx.x * 256 + threadIdx.x) * 4;
    if (i < n) {
        float4 v = *(const float4*)(in + i);
        *(__half2*)(o + i)     = __floats2half2_rn(v.x, v.y);
        *(__half2*)(o + i + 2) = __floats2half2_rn(v.z, v.w);
    }
}

// concat bq|bk -> g_bqk
__global__ void bcat_kernel(const float* __restrict__ bq,
                            const float* __restrict__ bk,
                            float* __restrict__ out)
{
    int i = blockIdx.x * 256 + threadIdx.x;     // 1024 threads total
    out[i] = (i < 512) ? bq[i] : bk[i - 512];
}

// ===========================================================================
// fp16 tensor-core GEMM (round-11 winner + issue-ahead 3):
// mma.sync.m16n8k16 + ldmatrix + 4-stage cp.async, 3 groups in flight.
//   D[m,n] = alpha * sum_k A[m*lda+k] * B[n*ldb+k] (+biasM[m]) (+biasN[n]) (+R)
// CTA tile 128x128, K-tile 32 halves (2 k16 steps), 4 warps (2x2),
// warp tile 64x64. smem row = 32 halves data in 40-half (80B) stride.
// Prologue fills stages 0-2; loop: wait_group 2 -> barrier -> ldm ->
// issue kt+3 -> mma. WAR-safe: stage (kt+3)&3's readers ran in iter kt-1,
// before this iteration's barrier. Dyn smem 81920 B, 2 CTAs/SM.
// ===========================================================================
#define TG_STAGE   20480u              // (A:10240 + B:10240) per stage
#define TG_B_OFF   10240u
#define TG_SMEM_BYTES 81920

template<bool HALF_C>
__global__ void __launch_bounds__(128, 2)
hgemm(const __half* __restrict__ A, const __half* __restrict__ B,
      void* __restrict__ Cv, int lda, int ldb, int ldc,
      long sA, long sB, long sC, long sR,
      int K, float alpha,
      const float* __restrict__ biasM, const float* __restrict__ biasN,
      const float* __restrict__ res)
{
    extern __shared__ __half sm[];
    const uint32_t sbase = s2u(sm);

    const int tid  = threadIdx.x;
    const int lane = tid & 31, wid = tid >> 5;
    const int m0 = blockIdx.y * 128, n0 = blockIdx.x * 128, bz = blockIdx.z;

    const __half* Ab = A + bz * sA + (long)m0 * lda;
    const __half* Bb = B + bz * sB + (long)n0 * ldb;

    // cp.async staging: rows r0+{0,32,64,96}, 16B chunk
    const int r0 = tid >> 2;            // 0..31
    const int c8 = (tid & 3) * 8;       // half-element offset (16B chunks)
    const uint32_t stDst = (uint32_t)(r0 * 80 + (tid & 3) * 16);
    const __half* pA = Ab + (long)r0 * lda + c8;
    const __half* pB = Bb + (long)r0 * ldb + c8;
    const long aS = (long)32 * lda;
    const long bS = (long)32 * ldb;

    // warp/fragment addressing: warp grid 2x2, warp tile 64x64
    const int qid = lane >> 2, rid = lane & 3;
    const int mw = (wid >> 1) * 64, nw = (wid & 1) * 64;
    const uint32_t aLD = sbase + (uint32_t)(mw + (lane & 15)) * 80u
                       + (uint32_t)((lane >> 4) & 1) * 16u;
    const uint32_t bLD = sbase + TG_B_OFF
        + (uint32_t)(nw + (lane & 7) + ((lane >> 4) & 1) * 8) * 80u
        + (uint32_t)((lane >> 3) & 1) * 16u;

    float d[4][8][4];
#pragma unroll
    for (int i = 0; i < 4; i++)
#pragma unroll
        for (int j = 0; j < 8; j++)
#pragma unroll
            for (int l = 0; l < 4; l++) d[i][j][l] = 0.f;

    const int NK = K >> 5;              // K-tile = 32 halves

    // prologue: stages 0,1,2
#pragma unroll
    for (int p = 0; p < 3; p++) {
        const uint32_t ao = sbase + (uint32_t)p * TG_STAGE + stDst;
        const __half* qa = pA + p * 32;
        const __half* qb = pB + p * 32;
#pragma unroll
        for (int i = 0; i < 4; i++) {
            cpa16(ao + (uint32_t)i * 2560u,            qa + i * aS);
            cpa16(ao + TG_B_OFF + (uint32_t)i * 2560u, qb + i * bS);
        }
        asm volatile("cp.async.commit_group;" ::: "memory");
    }

#pragma unroll 1
    for (int kt = 0; kt < NK; kt++) {
        const uint32_t bufo = (uint32_t)(kt & 3) * TG_STAGE;

        asm volatile("cp.async.wait_group 2;" ::: "memory");
        __syncthreads();

        // all fragments: 8 B-ldm.x4 + 8 A-ldm.x4 (2 k-steps)
        uint32_t bf[2][4][4], af[2][4][4];
#pragma unroll
        for (int ks = 0; ks < 2; ks++) {
#pragma unroll
            for (int nj = 0; nj < 4; nj++)
                ldm4(bf[ks][nj], bLD + bufo + (uint32_t)nj * 1280u
                                      + (uint32_t)ks * 32u);
#pragma unroll
            for (int mi = 0; mi < 4; mi++)
                ldm4(af[ks][mi], aLD + bufo + (uint32_t)mi * 1280u
                                      + (uint32_t)ks * 32u);
        }

        // issue loads for kt+3 (stage (kt+3)&3 = (kt-1)&3, readers done)
        if (kt + 3 < NK) {
            const uint32_t ao = sbase + (uint32_t)((kt + 3) & 3) * TG_STAGE + stDst;
            const __half* qa = pA + (kt + 3) * 32;
            const __half* qb = pB + (kt + 3) * 32;
#pragma unroll
            for (int i = 0; i < 4; i++) {
                cpa16(ao + (uint32_t)i * 2560u,            qa + i * aS);
                cpa16(ao + TG_B_OFF + (uint32_t)i * 2560u, qb + i * bS);
            }
        }
        asm volatile("cp.async.commit_group;" ::: "memory");

#pragma unroll
        for (int ks = 0; ks < 2; ks++)
#pragma unroll
            for (int mi = 0; mi < 4; mi++)
#pragma unroll
                for (int ni = 0; ni < 8; ni++)
                    mma16(d[mi][ni], af[ks][mi],
                          &bf[ks][ni >> 1][(ni & 1) * 2]);
        // no trailing barrier: top barrier + WAR argument above => safe
    }

    // epilogue
    const float* Rb = res ? (res + bz * sR) : nullptr;
#pragma unroll
    for (int mi = 0; mi < 4; mi++) {
        const int rA = m0 + mw + mi * 16 + qid;
        const int rB = rA + 8;
        const float bmA = biasM ? biasM[rA] : 0.f;
        const float bmB = biasM ? biasM[rB] : 0.f;
#pragma unroll
        for (int ni = 0; ni < 8; ni++) {
            const int col = n0 + nw + ni * 8 + rid * 2;
            float bn0 = 0.f, bn1 = 0.f;
            if (biasN) { bn0 = biasN[col]; bn1 = biasN[col + 1]; }
            float2 v0, v1;
            v0.x = d[mi][ni][0] * alpha + bmA + bn0;
            v0.y = d[mi][ni][1] * alpha + bmA + bn1;
            v1.x = d[mi][ni][2] * alpha + bmB + bn0;
            v1.y = d[mi][ni][3] * alpha + bmB + bn1;
            const long o0 = (long)rA * ldc + col;
            const long o1 = (long)rB * ldc + col;
            if (HALF_C) {
                __half* Ch = (__half*)Cv + bz * sC;
                *(__half2*)(Ch + o0) = __floats2half2_rn(v0.x, v0.y);
                *(__half2*)(Ch + o1) = __floats2half2_rn(v1.x, v1.y);
            } else {
                float* Cf = (float*)Cv + bz * sC;
                if (Rb) {
                    float2 ra = *(const float2*)(Rb + o0);
                    float2 rb = *(const float2*)(Rb + o1);
                    v0.x += ra.x; v0.y += ra.y;
                    v1.x += rb.x; v1.y += rb.y;
                }
                *(float2*)(Cf + o0) = v0;
                *(float2*)(Cf + o1) = v1;
            }
        }
    }
}

// ===========================================================================
// In-place register softmax over 4096 half scores -> half probs.
// ===========================================================================
__global__ void softmax_kernel(__half* __restrict__ s)
{
    const long row = blockIdx.x;
    __half* p = s + row * (long)NSP;
    const int tid = threadIdx.x;
    const int lane = tid & 31, wrp = tid >> 5;

    __shared__ float red[8];

    float v[16];
#pragma unroll
    for (int c = 0; c < 2; c++) {
        int4 pk = *(const int4*)(p + (tid + c * 256) * 8);
        const __half2* h2 = (const __half2*)&pk;
#pragma unroll
        for (int j = 0; j < 4; j++) {
            float2 f = __half22float2(h2[j]);
            v[c * 8 + j * 2]     = f.x;
            v[c * 8 + j * 2 + 1] = f.y;
        }
    }

    float m = v[0];
#pragma unroll
    for (int k = 1; k < 16; k++) m = fmaxf(m, v[k]);
#pragma unroll
    for (int o = 16; o > 0; o >>= 1)
        m = fmaxf(m, __shfl_xor_sync(0xffffffffu, m, o));
    if (lane == 0) red[wrp] = m;
    __syncthreads();
    m = red[lane & 7];
#pragma unroll
    for (int o = 4; o > 0; o >>= 1)
        m = fmaxf(m, __shfl_xor_sync(0xffffffffu, m, o));

    float sum = 0.f;
#pragma unroll
    for (int k = 0; k < 16; k++) {
        v[k] = __expf(v[k] - m);
        sum += v[k];
    }
#pragma unroll
    for (int o = 16; o > 0; o >>= 1)
        sum += __shfl_xor_sync(0xffffffffu, sum, o);
    __syncthreads();
    if (lane == 0) red[wrp] = sum;
    __syncthreads();
    sum = red[lane & 7];
#pragma unroll
    for (int o = 4; o > 0; o >>= 1)
        sum += __shfl_xor_sync(0xffffffffu, sum, o);
    const float inv = 1.f / sum;

#pragma unroll
    for (int c = 0; c < 2; c++) {
        int4 pk;
        __half2* h2 = (__half2*)&pk;
#pragma unroll
        for (int j = 0; j < 4; j++)
            h2[j] = __floats2half2_rn(v[c * 8 + j * 2] * inv,
                                      v[c * 8 + j * 2 + 1] * inv);
        *(int4*)(p + (tid + c * 256) * 8) = pk;
    }
}

// ===========================================================================
extern "C" void kernel_launch(void* const* d_in, const int* in_sizes, int n_in,
                              void* d_out, int out_size)
{
    const float* x     = (const float*)d_in[0];
    const float* gamma = (const float*)d_in[1];
    const float* beta  = (const float*)d_in[2];
    const float* wq    = (const float*)d_in[3];
    const float* bq    = (const float*)d_in[4];
    const float* wk    = (const float*)d_in[5];
    const float* bk    = (const float*)d_in[6];
    const float* wv    = (const float*)d_in[7];
    const float* bv    = (const float*)d_in[8];
    const float* wp    = (const float*)d_in[9];
    const float* bp    = (const float*)d_in[10];
    float* out = (float*)d_out;

    __half *pht, *pqk, *pv, *po, *pp, *pw;
    float *pmu, *prs, *pbqk;
    cudaGetSymbolAddress((void**)&pht,  g_ht);
    cudaGetSymbolAddress((void**)&pqk,  g_qk);
    cudaGetSymbolAddress((void**)&pv,   g_v);
    cudaGetSymbolAddress((void**)&po,   g_o);
    cudaGetSymbolAddress((void**)&pp,   g_p);
    cudaGetSymbolAddress((void**)&pw,   g_w);
    cudaGetSymbolAddress((void**)&pmu,  g_mu);
    cudaGetSymbolAddress((void**)&prs,  g_rsd);
    cudaGetSymbolAddress((void**)&pbqk, g_bqk);

    cudaFuncSetAttribute(hgemm<true>,  cudaFuncAttributeMaxDynamicSharedMemorySize,
                         TG_SMEM_BYTES);
    cudaFuncSetAttribute(hgemm<false>, cudaFuncAttributeMaxDynamicSharedMemorySize,
                         TG_SMEM_BYTES);

    const int WN = CCH * CCH;           // 262144
    __half* rwqk = pw;                  // wq rows 0-511, wk rows 512-1023
    __half* rwv  = pw + 2 * WN;
    __half* rwp  = pw + 3 * WN;

    // 0) convert weights to fp16 (one launch) + concat q/k biases
    tohalf4_kernel<<<dim3(WN / 1024, 4), 256>>>(wq, wk, wv, wp, pw, WN);
    bcat_kernel<<<4, 256>>>(bq, bk, pbqk);

    // 1) GroupNorm stats
    gn_stats<<<BATCH * GROUPS, 256>>>(x, pmu, prs);

    // 2) fused normalize + transpose -> h_t [N,C] (half)
    dim3 gT(NSP / 32, CCH / 32, BATCH);
    ntrans_kernel<<<gT, dim3(32, 8)>>>(x, gamma, beta, pmu, prs, pht);

    // 3) merged q|k: qk[i,o] = sum_c h_t[i,c] wqk[o,c] + bqk[o]
    //    (M=NSP, N=1024, K=CCH) -> [B][N][1024]
    dim3 gQK(1024 / 128, NSP / 128, BATCH);  // (8, 32, 4)
    hgemm<true><<<gQK, 128, TG_SMEM_BYTES>>>(pht, rwqk, pqk, CCH, CCH, 1024,
                                             CN, 0, QKS, 0,
                                             CCH, 1.f, nullptr, pbqk, nullptr);

    // 4) v[c,j] = sum_c' wv[c,c'] h_t[j,c'] + bv[c]  (M=CCH, N=NSP)
    dim3 gCN(NSP / 128, CCH / 128, BATCH);   // (32, 4, 4)
    hgemm<true><<<gCN, 128, TG_SMEM_BYTES>>>(rwv, pht, pv, CCH, CCH, NSP,
                                             0, CN, CN, 0,
                                             CCH, 1.f, bv, nullptr, nullptr);

    // 5) scores S[i,j] = scale * sum_c q[i,c] k[j,c] -> half, into g_p
    //    A = qk cols 0-511 (q), B = qk cols 512-1023 (k); lda=ldb=1024
    const float scale = 0.04419417382415922f;  // 512^-0.5
    dim3 gSS(NSP / 128, NSP / 128, BATCH);   // (32, 32, 4)
    hgemm<true><<<gSS, 128, TG_SMEM_BYTES>>>(pqk, pqk + 512, pp, 1024, 1024, NSP,
                                             QKS, QKS, NNL, 0,
                                             CCH, scale, nullptr, nullptr, nullptr);

    // 6) in-place softmax over keys (half -> half)
    softmax_kernel<<<BATCH * NSP, 256>>>(pp);

    // 7) O_t[i,c] = sum_j P[i,j] v[c,j]   (M=NSP, N=CCH, K=NSP)
    dim3 gNC(CCH / 128, NSP / 128, BATCH);   // (4, 32, 4)
    hgemm<true><<<gNC, 128, TG_SMEM_BYTES>>>(pp, pv, po, NSP, NSP, CCH,
                                             NNL, CN, CN, 0,
                                             NSP, 1.f, nullptr, nullptr, nullptr);

    // 8) out[o,n] = sum_c wp[o,c] O_t[n,c] + bp[o] + x[o,n]  (M=CCH, N=NSP)
    hgemm<false><<<gCN, 128, TG_SMEM_BYTES>>>(rwp, po, out, CCH, CCH, NSP,
                                              0, CN, CN, CN,
                                              CCH, 1.f, bp, nullptr, x);
}

// round 15
// speedup vs baseline: 1.1466x; 1.0279x over previous
#include <cuda_runtime.h>
#include <cuda_fp16.h>
#include <cstdint>
#include <math.h>

#define BATCH 4
#define CCH   512
#define NSP   4096
#define GROUPS 32
#define GSIZE  65536

static const long CN  = (long)CCH * NSP;
static const long NNL = (long)NSP * NSP;
static const long QKS = (long)NSP * 1024;   // per-batch stride of merged q|k

// Scratch (device globals — allocation-free per harness rules)
__device__ __half g_ht[BATCH * CCH * NSP];   // normalized h transposed [B][N][C]
__device__ __half g_qk[BATCH * NSP * 1024];  // q|k merged [B][N][2C]
__device__ __half g_v [BATCH * CCH * NSP];   // v   [B][C][N]
__device__ __half g_o [BATCH * CCH * NSP];   // O_t [B][N][C]
__device__ __half g_p [BATCH * NSP * NSP];   // E = exp(scores) (half)
__device__ __half g_w [4 * CCH * CCH];       // half wq,wk,wv,wp (wq,wk adjacent)
__device__ float  g_bqk[1024];               // concat bq|bk
__device__ float  g_rsum[BATCH * NSP];       // 1 / rowsum(E)
__device__ float  g_mu [BATCH * GROUPS];
__device__ float  g_rsd[BATCH * GROUPS];

// ===========================================================================
// helpers
// ===========================================================================
__device__ __forceinline__ uint32_t s2u(const void* p) {
    uint32_t a;
    asm("{ .reg .u64 t; cvta.to.shared.u64 t, %1; cvt.u32.u64 %0, t; }"
        : "=r"(a) : "l"(p));
    return a;
}
__device__ __forceinline__ void cpa16(uint32_t d, const void* s) {
    asm volatile("cp.async.cg.shared.global [%0], [%1], 16;" :: "r"(d), "l"(s));
}
__device__ __forceinline__ void mma16(float* d, const uint32_t* a, const uint32_t* b) {
    asm volatile(
        "mma.sync.aligned.m16n8k16.row.col.f32.f16.f16.f32 "
        "{%0,%1,%2,%3}, {%4,%5,%6,%7}, {%8,%9}, {%0,%1,%2,%3};"
        : "+f"(d[0]), "+f"(d[1]), "+f"(d[2]), "+f"(d[3])
        : "r"(a[0]), "r"(a[1]), "r"(a[2]), "r"(a[3]), "r"(b[0]), "r"(b[1]));
}
__device__ __forceinline__ void ldm4(uint32_t* r, uint32_t addr) {
    asm volatile(
        "ldmatrix.sync.aligned.m8n8.x4.shared.b16 {%0,%1,%2,%3}, [%4];"
        : "=r"(r[0]), "=r"(r[1]), "=r"(r[2]), "=r"(r[3]) : "r"(addr));
}

// ===========================================================================
// GroupNorm stats: one block per (b, group); writes mu/rstd only.
// ===========================================================================
__global__ void gn_stats(const float* __restrict__ x,
                         float* __restrict__ mu_out,
                         float* __restrict__ rsd_out)
{
    const int bg  = blockIdx.x;
    const long base = (long)bg * GSIZE;
    const int tid = threadIdx.x;

    float s = 0.f, ss = 0.f;
    for (int i = tid * 4; i < GSIZE; i += 256 * 4) {
        float4 v = *(const float4*)(x + base + i);
        s  += v.x + v.y + v.z + v.w;
        ss += v.x*v.x + v.y*v.y + v.z*v.z + v.w*v.w;
    }
    __shared__ float rs[256], rq[256];
    rs[tid] = s; rq[tid] = ss;
    __syncthreads();
    for (int o = 128; o > 0; o >>= 1) {
        if (tid < o) { rs[tid] += rs[tid + o]; rq[tid] += rq[tid + o]; }
        __syncthreads();
    }
    if (tid == 0) {
        float mu  = rs[0] * (1.f / GSIZE);
        float var = rq[0] * (1.f / GSIZE) - mu * mu;
        mu_out[bg]  = mu;
        rsd_out[bg] = rsqrtf(var + 1e-6f);
    }
}

// ===========================================================================
// Fused normalize + transpose + fp16 convert: x[C,N] -> h_t[N,C] (half)
// ===========================================================================
__global__ void ntrans_kernel(const float* __restrict__ x,
                              const float* __restrict__ gamma,
                              const float* __restrict__ beta,
                              const float* __restrict__ mu,
                              const float* __restrict__ rsd,
                              __half* __restrict__ out)
{
    __shared__ float t[32][33];
    const int bz = blockIdx.z;
    const float* I = x + (long)bz * CN;
    __half* O = out + (long)bz * CN;
    const int c0 = blockIdx.y * 32, n0 = blockIdx.x * 32;
    const int tx = threadIdx.x, ty = threadIdx.y;   // (32, 8)
#pragma unroll
    for (int i = 0; i < 32; i += 8) {
        const int c = c0 + ty + i;
        const int bg = bz * GROUPS + (c >> 4);      // 16 channels per group
        const float ga = gamma[c] * rsd[bg];
        const float be = beta[c] - mu[bg] * ga;
        t[ty + i][tx] = I[(long)c * NSP + n0 + tx] * ga + be;
    }
    __syncthreads();
#pragma unroll
    for (int i = 0; i < 32; i += 8)
        O[(long)(n0 + ty + i) * CCH + c0 + tx] = __float2half_rn(t[tx][ty + i]);
}

// ===========================================================================
// fp32 -> fp16 convert: all 4 weight matrices in one launch (blockIdx.y picks)
// ===========================================================================
__global__ void tohalf4_kernel(const float* __restrict__ w0,
                               const float* __restrict__ w1,
                               const float* __restrict__ w2,
                               const float* __restrict__ w3,
                               __half* __restrict__ out, int n)
{
    const float* in = (blockIdx.y == 0) ? w0 : (blockIdx.y == 1) ? w1
                    : (blockIdx.y == 2) ? w2 : w3;
    __half* o = out + (long)blockIdx.y * n;
    int i = (blockIdx.x * 256 + threadIdx.x) * 4;
    if (i < n) {
        float4 v = *(const float4*)(in + i);
        *(__half2*)(o + i)     = __floats2half2_rn(v.x, v.y);
        *(__half2*)(o + i + 2) = __floats2half2_rn(v.z, v.w);
    }
}

// concat bq|bk -> g_bqk
__global__ void bcat_kernel(const float* __restrict__ bq,
                            const float* __restrict__ bk,
                            float* __restrict__ out)
{
    int i = blockIdx.x * 256 + threadIdx.x;     // 1024 threads total
    out[i] = (i < 512) ? bq[i] : bk[i - 512];
}

// ===========================================================================
// fp16 tensor-core GEMM (round-11 winning loop):
// mma.sync.m16n8k16 + ldmatrix + 4-stage cp.async, issue-ahead 2.
//   D[m,n] = alpha*sum_k A[m,k]B[n,k] (+biasM[m])(+biasN[n])(+R)
//   then optionally *rowScale[m], optionally exp(), stored half or float.
// CTA tile 128x128, K-tile 32 halves, 4 warps (2x2), warp tile 64x64.
// smem row = 32 halves data in 40-half (80B) stride. Dyn smem 81920 B.
// ===========================================================================
#define TG_STAGE   20480u              // (A:10240 + B:10240) per stage
#define TG_B_OFF   10240u
#define TG_SMEM_BYTES 81920

template<bool HALF_C, bool EXP_C>
__global__ void __launch_bounds__(128, 2)
hgemm(const __half* __restrict__ A, const __half* __restrict__ B,
      void* __restrict__ Cv, int lda, int ldb, int ldc,
      long sA, long sB, long sC, long sR,
      int K, float alpha,
      const float* __restrict__ biasM, const float* __restrict__ biasN,
      const float* __restrict__ res,
      const float* __restrict__ rowScale, long sRS)
{
    extern __shared__ __half sm[];
    const uint32_t sbase = s2u(sm);

    const int tid  = threadIdx.x;
    const int lane = tid & 31, wid = tid >> 5;
    const int m0 = blockIdx.y * 128, n0 = blockIdx.x * 128, bz = blockIdx.z;

    const __half* Ab = A + bz * sA + (long)m0 * lda;
    const __half* Bb = B + bz * sB + (long)n0 * ldb;

    // cp.async staging: rows r0+{0,32,64,96}, 16B chunk
    const int r0 = tid >> 2;            // 0..31
    const int c8 = (tid & 3) * 8;       // half-element offset (16B chunks)
    const uint32_t stDst = (uint32_t)(r0 * 80 + (tid & 3) * 16);
    const __half* pA = Ab + (long)r0 * lda + c8;
    const __half* pB = Bb + (long)r0 * ldb + c8;
    const long aS = (long)32 * lda;
    const long bS = (long)32 * ldb;

    // warp/fragment addressing: warp grid 2x2, warp tile 64x64
    const int qid = lane >> 2, rid = lane & 3;
    const int mw = (wid >> 1) * 64, nw = (wid & 1) * 64;
    const uint32_t aLD = sbase + (uint32_t)(mw + (lane & 15)) * 80u
                       + (uint32_t)((lane >> 4) & 1) * 16u;
    const uint32_t bLD = sbase + TG_B_OFF
        + (uint32_t)(nw + (lane & 7) + ((lane >> 4) & 1) * 8) * 80u
        + (uint32_t)((lane >> 3) & 1) * 16u;

    float d[4][8][4];
#pragma unroll
    for (int i = 0; i < 4; i++)
#pragma unroll
        for (int j = 0; j < 8; j++)
#pragma unroll
            for (int l = 0; l < 4; l++) d[i][j][l] = 0.f;

    const int NK = K >> 5;              // K-tile = 32 halves

    // prologue: stages 0,1
#pragma unroll
    for (int p = 0; p < 2; p++) {
        const uint32_t ao = sbase + (uint32_t)p * TG_STAGE + stDst;
        const __half* qa = pA + p * 32;
        const __half* qb = pB + p * 32;
#pragma unroll
        for (int i = 0; i < 4; i++) {
            cpa16(ao + (uint32_t)i * 2560u,            qa + i * aS);
            cpa16(ao + TG_B_OFF + (uint32_t)i * 2560u, qb + i * bS);
        }
        asm volatile("cp.async.commit_group;" ::: "memory");
    }

#pragma unroll 1
    for (int kt = 0; kt < NK; kt++) {
        const uint32_t bufo = (uint32_t)(kt & 3) * TG_STAGE;

        asm volatile("cp.async.wait_group 1;" ::: "memory");
        __syncthreads();

        // all fragments: 8 B-ldm.x4 + 8 A-ldm.x4 (2 k-steps)
        uint32_t bf[2][4][4], af[2][4][4];
#pragma unroll
        for (int ks = 0; ks < 2; ks++) {
#pragma unroll
            for (int nj = 0; nj < 4; nj++)
                ldm4(bf[ks][nj], bLD + bufo + (uint32_t)nj * 1280u
                                      + (uint32_t)ks * 32u);
#pragma unroll
            for (int mi = 0; mi < 4; mi++)
                ldm4(af[ks][mi], aLD + bufo + (uint32_t)mi * 1280u
                                      + (uint32_t)ks * 32u);
        }

        // issue loads for kt+2
        if (kt + 2 < NK) {
            const uint32_t ao = sbase + (uint32_t)((kt + 2) & 3) * TG_STAGE + stDst;
            const __half* qa = pA + (kt + 2) * 32;
            const __half* qb = pB + (kt + 2) * 32;
#pragma unroll
            for (int i = 0; i < 4; i++) {
                cpa16(ao + (uint32_t)i * 2560u,            qa + i * aS);
                cpa16(ao + TG_B_OFF + (uint32_t)i * 2560u, qb + i * bS);
            }
        }
        asm volatile("cp.async.commit_group;" ::: "memory");

#pragma unroll
        for (int ks = 0; ks < 2; ks++)
#pragma unroll
            for (int mi = 0; mi < 4; mi++)
#pragma unroll
                for (int ni = 0; ni < 8; ni++)
                    mma16(d[mi][ni], af[ks][mi],
                          &bf[ks][ni >> 1][(ni & 1) * 2]);
        // no trailing barrier: 4 stages + issue-ahead 2 + top barrier => safe
    }

    // epilogue
    const float* Rb = res ? (res + bz * sR) : nullptr;
    const float* RS = rowScale ? (rowScale + bz * sRS) : nullptr;
#pragma unroll
    for (int mi = 0; mi < 4; mi++) {
        const int rA = m0 + mw + mi * 16 + qid;
        const int rB = rA + 8;
        const float bmA = biasM ? biasM[rA] : 0.f;
        const float bmB = biasM ? biasM[rB] : 0.f;
        const float rsA = RS ? RS[rA] : 1.f;
        const float rsB = RS ? RS[rB] : 1.f;
#pragma unroll
        for (int ni = 0; ni < 8; ni++) {
            const int col = n0 + nw + ni * 8 + rid * 2;
            float bn0 = 0.f, bn1 = 0.f;
            if (biasN) { bn0 = biasN[col]; bn1 = biasN[col + 1]; }
            float2 v0, v1;
            v0.x = d[mi][ni][0] * alpha + bmA + bn0;
            v0.y = d[mi][ni][1] * alpha + bmA + bn1;
            v1.x = d[mi][ni][2] * alpha + bmB + bn0;
            v1.y = d[mi][ni][3] * alpha + bmB + bn1;
            if (RS) {
                v0.x *= rsA; v0.y *= rsA;
                v1.x *= rsB; v1.y *= rsB;
            }
            if (EXP_C) {
                v0.x = __expf(v0.x); v0.y = __expf(v0.y);
                v1.x = __expf(v1.x); v1.y = __expf(v1.y);
            }
            const long o0 = (long)rA * ldc + col;
            const long o1 = (long)rB * ldc + col;
            if (HALF_C) {
                __half* Ch = (__half*)Cv + bz * sC;
                *(__half2*)(Ch + o0) = __floats2half2_rn(v0.x, v0.y);
                *(__half2*)(Ch + o1) = __floats2half2_rn(v1.x, v1.y);
            } else {
                float* Cf = (float*)Cv + bz * sC;
                if (Rb) {
                    float2 ra = *(const float2*)(Rb + o0);
                    float2 rb = *(const float2*)(Rb + o1);
                    v0.x += ra.x; v0.y += ra.y;
                    v1.x += rb.x; v1.y += rb.y;
                }
                *(float2*)(Cf + o0) = v0;
                *(float2*)(Cf + o1) = v1;
            }
        }
    }
}

// ===========================================================================
// Row sum of E (half) -> reciprocal (float). One block per row.
// ===========================================================================
__global__ void rowsum_kernel(const __half* __restrict__ e,
                              float* __restrict__ rinv)
{
    const long row = blockIdx.x;
    const __half* p = e + row * (long)NSP;
    const int tid = threadIdx.x;
    const int lane = tid & 31, wrp = tid >> 5;

    __shared__ float red[8];

    float sum = 0.f;
#pragma unroll
    for (int c = 0; c < 2; c++) {
        int4 pk = *(const int4*)(p + (tid + c * 256) * 8);
        const __half2* h2 = (const __half2*)&pk;
#pragma unroll
        for (int j = 0; j < 4; j++) {
            float2 f = __half22float2(h2[j]);
            sum += f.x + f.y;
        }
    }
#pragma unroll
    for (int o = 16; o > 0; o >>= 1)
        sum += __shfl_xor_sync(0xffffffffu, sum, o);
    if (lane == 0) red[wrp] = sum;
    __syncthreads();
    if (tid == 0) {
        float s = 0.f;
#pragma unroll
        for (int w = 0; w < 8; w++) s += red[w];
        rinv[row] = 1.f / s;
    }
}

// ===========================================================================
extern "C" void kernel_launch(void* const* d_in, const int* in_sizes, int n_in,
                              void* d_out, int out_size)
{
    const float* x     = (const float*)d_in[0];
    const float* gamma = (const float*)d_in[1];
    const float* beta  = (const float*)d_in[2];
    const float* wq    = (const float*)d_in[3];
    const float* bq    = (const float*)d_in[4];
    const float* wk    = (const float*)d_in[5];
    const float* bk    = (const float*)d_in[6];
    const float* wv    = (const float*)d_in[7];
    const float* bv    = (const float*)d_in[8];
    const float* wp    = (const float*)d_in[9];
    const float* bp    = (const float*)d_in[10];
    float* out = (float*)d_out;

    __half *pht, *pqk, *pv, *po, *pp, *pw;
    float *pmu, *prs, *pbqk, *prsum;
    cudaGetSymbolAddress((void**)&pht,   g_ht);
    cudaGetSymbolAddress((void**)&pqk,   g_qk);
    cudaGetSymbolAddress((void**)&pv,    g_v);
    cudaGetSymbolAddress((void**)&po,    g_o);
    cudaGetSymbolAddress((void**)&pp,    g_p);
    cudaGetSymbolAddress((void**)&pw,    g_w);
    cudaGetSymbolAddress((void**)&pmu,   g_mu);
    cudaGetSymbolAddress((void**)&prs,   g_rsd);
    cudaGetSymbolAddress((void**)&pbqk,  g_bqk);
    cudaGetSymbolAddress((void**)&prsum, g_rsum);

    cudaFuncSetAttribute((const void*)hgemm<true, false>,
                         cudaFuncAttributeMaxDynamicSharedMemorySize, TG_SMEM_BYTES);
    cudaFuncSetAttribute((const void*)hgemm<true, true>,
                         cudaFuncAttributeMaxDynamicSharedMemorySize, TG_SMEM_BYTES);
    cudaFuncSetAttribute((const void*)hgemm<false, false>,
                         cudaFuncAttributeMaxDynamicSharedMemorySize, TG_SMEM_BYTES);

    const int WN = CCH * CCH;           // 262144
    __half* rwqk = pw;                  // wq rows 0-511, wk rows 512-1023
    __half* rwv  = pw + 2 * WN;
    __half* rwp  = pw + 3 * WN;

    // 0) convert weights to fp16 (one launch) + concat q/k biases
    tohalf4_kernel<<<dim3(WN / 1024, 4), 256>>>(wq, wk, wv, wp, pw, WN);
    bcat_kernel<<<4, 256>>>(bq, bk, pbqk);

    // 1) GroupNorm stats
    gn_stats<<<BATCH * GROUPS, 256>>>(x, pmu, prs);

    // 2) fused normalize + transpose -> h_t [N,C] (half)
    dim3 gT(NSP / 32, CCH / 32, BATCH);
    ntrans_kernel<<<gT, dim3(32, 8)>>>(x, gamma, beta, pmu, prs, pht);

    // 3) merged q|k: qk[i,o] = sum_c h_t[i,c] wqk[o,c] + bqk[o]
    dim3 gQK(1024 / 128, NSP / 128, BATCH);  // (8, 32, 4)
    hgemm<true, false><<<gQK, 128, TG_SMEM_BYTES>>>(
        pht, rwqk, pqk, CCH, CCH, 1024, CN, 0, QKS, 0,
        CCH, 1.f, nullptr, pbqk, nullptr, nullptr, 0);

    // 4) v[c,j] = sum_c' wv[c,c'] h_t[j,c'] + bv[c]  (M=CCH, N=NSP)
    dim3 gCN(NSP / 128, CCH / 128, BATCH);   // (32, 4, 4)
    hgemm<true, false><<<gCN, 128, TG_SMEM_BYTES>>>(
        rwv, pht, pv, CCH, CCH, NSP, 0, CN, CN, 0,
        CCH, 1.f, bv, nullptr, nullptr, nullptr, 0);

    // 5) E[i,j] = exp(scale * q[i]·k[j]) -> half into g_p (no max shift;
    //    scores ~ N(0,1), max ~ 6 -> e^6 ≈ 400 fits half comfortably)
    const float scale = 0.04419417382415922f;  // 512^-0.5
    dim3 gSS(NSP / 128, NSP / 128, BATCH);   // (32, 32, 4)
    hgemm<true, true><<<gSS, 128, TG_SMEM_BYTES>>>(
        pqk, pqk + 512, pp, 1024, 1024, NSP, QKS, QKS, NNL, 0,
        CCH, scale, nullptr, nullptr, nullptr, nullptr, 0);

    // 6) row reciprocal sums of E
    rowsum_kernel<<<BATCH * NSP, 256>>>(pp, prsum);

    // 7) O_t[i,c] = (sum_j E[i,j] v[c,j]) * rinv[i]  (M=NSP, N=CCH, K=NSP)
    dim3 gNC(CCH / 128, NSP / 128, BATCH);   // (4, 32, 4)
    hgemm<true, false><<<gNC, 128, TG_SMEM_BYTES>>>(
        pp, pv, po, NSP, NSP, CCH, NNL, CN, CN, 0,
        NSP, 1.f, nullptr, nullptr, nullptr, prsum, NSP);

    // 8) out[o,n] = sum_c wp[o,c] O_t[n,c] + bp[o] + x[o,n]  (M=CCH, N=NSP)
    hgemm<false, false><<<gCN, 128, TG_SMEM_BYTES>>>(
        rwp, po, out, CCH, CCH, NSP, 0, CN, CN, CN,
        CCH, 1.f, bp, nullptr, x, nullptr, 0);
}

// round 16
// speedup vs baseline: 1.1909x; 1.0386x over previous
#include <cuda_runtime.h>
#include <cuda_fp16.h>
#include <cstdint>
#include <math.h>

#define BATCH 4
#define CCH   512
#define NSP   4096
#define GROUPS 32
#define GSIZE  65536

static const long CN  = (long)CCH * NSP;
static const long NNL = (long)NSP * NSP;
static const long QKS = (long)NSP * 1024;   // per-batch stride of merged q|k

// Scratch (device globals — allocation-free per harness rules)
__device__ __half g_ht[BATCH * CCH * NSP];   // normalized h transposed [B][N][C]
__device__ __half g_qk[BATCH * NSP * 1024];  // q|k merged [B][N][2C]
__device__ __half g_v [BATCH * CCH * NSP];   // v   [B][C][N]
__device__ __half g_o [BATCH * CCH * NSP];   // O_t [B][N][C]
__device__ __half g_p [BATCH * NSP * NSP];   // E = exp(scores) (half)
__device__ __half g_w [4 * CCH * CCH];       // half wq,wk,wv,wp (wq,wk adjacent)
__device__ float  g_bqk[1024];               // concat bq|bk
__device__ float  g_rsum[BATCH * NSP];       // rowsum(E), built via atomics
__device__ float  g_mu [BATCH * GROUPS];
__device__ float  g_rsd[BATCH * GROUPS];

// ===========================================================================
// helpers
// ===========================================================================
__device__ __forceinline__ uint32_t s2u(const void* p) {
    uint32_t a;
    asm("{ .reg .u64 t; cvta.to.shared.u64 t, %1; cvt.u32.u64 %0, t; }"
        : "=r"(a) : "l"(p));
    return a;
}
__device__ __forceinline__ void cpa16(uint32_t d, const void* s) {
    asm volatile("cp.async.cg.shared.global [%0], [%1], 16;" :: "r"(d), "l"(s));
}
__device__ __forceinline__ void mma16(float* d, const uint32_t* a, const uint32_t* b) {
    asm volatile(
        "mma.sync.aligned.m16n8k16.row.col.f32.f16.f16.f32 "
        "{%0,%1,%2,%3}, {%4,%5,%6,%7}, {%8,%9}, {%0,%1,%2,%3};"
        : "+f"(d[0]), "+f"(d[1]), "+f"(d[2]), "+f"(d[3])
        : "r"(a[0]), "r"(a[1]), "r"(a[2]), "r"(a[3]), "r"(b[0]), "r"(b[1]));
}
__device__ __forceinline__ void ldm4(uint32_t* r, uint32_t addr) {
    asm volatile(
        "ldmatrix.sync.aligned.m8n8.x4.shared.b16 {%0,%1,%2,%3}, [%4];"
        : "=r"(r[0]), "=r"(r[1]), "=r"(r[2]), "=r"(r[3]) : "r"(addr));
}

// ===========================================================================
// GroupNorm stats: one block per (b, group); writes mu/rstd only.
// ===========================================================================
__global__ void gn_stats(const float* __restrict__ x,
                         float* __restrict__ mu_out,
                         float* __restrict__ rsd_out)
{
    const int bg  = blockIdx.x;
    const long base = (long)bg * GSIZE;
    const int tid = threadIdx.x;

    float s = 0.f, ss = 0.f;
    for (int i = tid * 4; i < GSIZE; i += 256 * 4) {
        float4 v = *(const float4*)(x + base + i);
        s  += v.x + v.y + v.z + v.w;
        ss += v.x*v.x + v.y*v.y + v.z*v.z + v.w*v.w;
    }
    __shared__ float rs[256], rq[256];
    rs[tid] = s; rq[tid] = ss;
    __syncthreads();
    for (int o = 128; o > 0; o >>= 1) {
        if (tid < o) { rs[tid] += rs[tid + o]; rq[tid] += rq[tid + o]; }
        __syncthreads();
    }
    if (tid == 0) {
        float mu  = rs[0] * (1.f / GSIZE);
        float var = rq[0] * (1.f / GSIZE) - mu * mu;
        mu_out[bg]  = mu;
        rsd_out[bg] = rsqrtf(var + 1e-6f);
    }
}

// ===========================================================================
// Fused normalize + transpose + fp16 convert: x[C,N] -> h_t[N,C] (half)
// 256 threads; loads as (32,8), stores half2 as (16,16).
// ===========================================================================
__global__ void __launch_bounds__(256)
ntrans_kernel(const float* __restrict__ x,
              const float* __restrict__ gamma,
              const float* __restrict__ beta,
              const float* __restrict__ mu,
              const float* __restrict__ rsd,
              __half* __restrict__ out)
{
    __shared__ float t[32][33];
    const int bz = blockIdx.z;
    const float* I = x + (long)bz * CN;
    __half* O = out + (long)bz * CN;
    const int c0 = blockIdx.y * 32, n0 = blockIdx.x * 32;
    const int tid = threadIdx.x;

    // load: (tx, ty) = (tid&31, tid>>5)
    {
        const int tx = tid & 31, ty = tid >> 5;
#pragma unroll
        for (int i = 0; i < 32; i += 8) {
            const int c = c0 + ty + i;
            const int bg = bz * GROUPS + (c >> 4);
            const float ga = gamma[c] * rsd[bg];
            const float be = beta[c] - mu[bg] * ga;
            t[ty + i][tx] = I[(long)c * NSP + n0 + tx] * ga + be;
        }
    }
    __syncthreads();
    // store: (cx, ny) = (tid&15, tid>>4); half2 over c
    {
        const int cx = tid & 15, ny = tid >> 4;
#pragma unroll
        for (int i = 0; i < 2; i++) {
            const int nw = ny + i * 16;
            __half2 hv = __floats2half2_rn(t[cx * 2][nw], t[cx * 2 + 1][nw]);
            *(__half2*)(O + (long)(n0 + nw) * CCH + c0 + cx * 2) = hv;
        }
    }
}

// ===========================================================================
// fp32 -> fp16 convert: all 4 weight matrices in one launch (blockIdx.y picks)
// ===========================================================================
__global__ void tohalf4_kernel(const float* __restrict__ w0,
                               const float* __restrict__ w1,
                               const float* __restrict__ w2,
                               const float* __restrict__ w3,
                               __half* __restrict__ out, int n)
{
    const float* in = (blockIdx.y == 0) ? w0 : (blockIdx.y == 1) ? w1
                    : (blockIdx.y == 2) ? w2 : w3;
    __half* o = out + (long)blockIdx.y * n;
    int i = (blockIdx.x * 256 + threadIdx.x) * 4;
    if (i < n) {
        float4 v = *(const float4*)(in + i);
        *(__half2*)(o + i)     = __floats2half2_rn(v.x, v.y);
        *(__half2*)(o + i + 2) = __floats2half2_rn(v.z, v.w);
    }
}

// concat bq|bk -> g_bqk
__global__ void bcat_kernel(const float* __restrict__ bq,
                            const float* __restrict__ bk,
                            float* __restrict__ out)
{
    int i = blockIdx.x * 256 + threadIdx.x;     // 1024 threads total
    out[i] = (i < 512) ? bq[i] : bk[i - 512];
}

// ===========================================================================
// fp16 tensor-core GEMM (round-11 winning loop):
// mma.sync.m16n8k16 + ldmatrix + 4-stage cp.async, issue-ahead 2.
//   D[m,n] = alpha*sum_k A[m,k]B[n,k] (+biasM[m])(+biasN[n])(+R)
//   EXP_C: store exp(D) and atomically accumulate row sums into rsumOut.
//   RS_RECIP: multiply by 1/rowScale[m] (rowScale = raw sums).
// CTA tile 128x128, K-tile 32 halves, 4 warps (2x2), warp tile 64x64.
// smem row = 32 halves data in 40-half (80B) stride. Dyn smem 81920 B.
// ===========================================================================
#define TG_STAGE   20480u              // (A:10240 + B:10240) per stage
#define TG_B_OFF   10240u
#define TG_SMEM_BYTES 81920

template<bool HALF_C, bool EXP_C, bool RS_RECIP>
__global__ void __launch_bounds__(128, 2)
hgemm(const __half* __restrict__ A, const __half* __restrict__ B,
      void* __restrict__ Cv, int lda, int ldb, int ldc,
      long sA, long sB, long sC, long sR,
      int K, float alpha,
      const float* __restrict__ biasM, const float* __restrict__ biasN,
      const float* __restrict__ res,
      const float* __restrict__ rowScale, long sRS,
      float* __restrict__ rsumOut, long sRO)
{
    extern __shared__ __half sm[];
    const uint32_t sbase = s2u(sm);

    const int tid  = threadIdx.x;
    const int lane = tid & 31, wid = tid >> 5;
    const int m0 = blockIdx.y * 128, n0 = blockIdx.x * 128, bz = blockIdx.z;

    const __half* Ab = A + bz * sA + (long)m0 * lda;
    const __half* Bb = B + bz * sB + (long)n0 * ldb;

    // cp.async staging: rows r0+{0,32,64,96}, 16B chunk
    const int r0 = tid >> 2;            // 0..31
    const int c8 = (tid & 3) * 8;       // half-element offset (16B chunks)
    const uint32_t stDst = (uint32_t)(r0 * 80 + (tid & 3) * 16);
    const __half* pA = Ab + (long)r0 * lda + c8;
    const __half* pB = Bb + (long)r0 * ldb + c8;
    const long aS = (long)32 * lda;
    const long bS = (long)32 * ldb;

    // warp/fragment addressing: warp grid 2x2, warp tile 64x64
    const int qid = lane >> 2, rid = lane & 3;
    const int mw = (wid >> 1) * 64, nw = (wid & 1) * 64;
    const uint32_t aLD = sbase + (uint32_t)(mw + (lane & 15)) * 80u
                       + (uint32_t)((lane >> 4) & 1) * 16u;
    const uint32_t bLD = sbase + TG_B_OFF
        + (uint32_t)(nw + (lane & 7) + ((lane >> 4) & 1) * 8) * 80u
        + (uint32_t)((lane >> 3) & 1) * 16u;

    float d[4][8][4];
#pragma unroll
    for (int i = 0; i < 4; i++)
#pragma unroll
        for (int j = 0; j < 8; j++)
#pragma unroll
            for (int l = 0; l < 4; l++) d[i][j][l] = 0.f;

    const int NK = K >> 5;              // K-tile = 32 halves

    // prologue: stages 0,1
#pragma unroll
    for (int p = 0; p < 2; p++) {
        const uint32_t ao = sbase + (uint32_t)p * TG_STAGE + stDst;
        const __half* qa = pA + p * 32;
        const __half* qb = pB + p * 32;
#pragma unroll
        for (int i = 0; i < 4; i++) {
            cpa16(ao + (uint32_t)i * 2560u,            qa + i * aS);
            cpa16(ao + TG_B_OFF + (uint32_t)i * 2560u, qb + i * bS);
        }
        asm volatile("cp.async.commit_group;" ::: "memory");
    }

#pragma unroll 1
    for (int kt = 0; kt < NK; kt++) {
        const uint32_t bufo = (uint32_t)(kt & 3) * TG_STAGE;

        asm volatile("cp.async.wait_group 1;" ::: "memory");
        __syncthreads();

        // all fragments: 8 B-ldm.x4 + 8 A-ldm.x4 (2 k-steps)
        uint32_t bf[2][4][4], af[2][4][4];
#pragma unroll
        for (int ks = 0; ks < 2; ks++) {
#pragma unroll
            for (int nj = 0; nj < 4; nj++)
                ldm4(bf[ks][nj], bLD + bufo + (uint32_t)nj * 1280u
                                      + (uint32_t)ks * 32u);
#pragma unroll
            for (int mi = 0; mi < 4; mi++)
                ldm4(af[ks][mi], aLD + bufo + (uint32_t)mi * 1280u
                                      + (uint32_t)ks * 32u);
        }

        // issue loads for kt+2
        if (kt + 2 < NK) {
            const uint32_t ao = sbase + (uint32_t)((kt + 2) & 3) * TG_STAGE + stDst;
            const __half* qa = pA + (kt + 2) * 32;
            const __half* qb = pB + (kt + 2) * 32;
#pragma unroll
            for (int i = 0; i < 4; i++) {
                cpa16(ao + (uint32_t)i * 2560u,            qa + i * aS);
                cpa16(ao + TG_B_OFF + (uint32_t)i * 2560u, qb + i * bS);
            }
        }
        asm volatile("cp.async.commit_group;" ::: "memory");

#pragma unroll
        for (int ks = 0; ks < 2; ks++)
#pragma unroll
            for (int mi = 0; mi < 4; mi++)
#pragma unroll
                for (int ni = 0; ni < 8; ni++)
                    mma16(d[mi][ni], af[ks][mi],
                          &bf[ks][ni >> 1][(ni & 1) * 2]);
        // no trailing barrier: 4 stages + issue-ahead 2 + top barrier => safe
    }

    // epilogue
    const float* Rb = res ? (res + bz * sR) : nullptr;
    const float* RS = rowScale ? (rowScale + bz * sRS) : nullptr;
    float* RO = EXP_C ? (rsumOut + bz * sRO) : nullptr;
#pragma unroll
    for (int mi = 0; mi < 4; mi++) {
        const int rA = m0 + mw + mi * 16 + qid;
        const int rB = rA + 8;
        const float bmA = biasM ? biasM[rA] : 0.f;
        const float bmB = biasM ? biasM[rB] : 0.f;
        float rsA = 1.f, rsB = 1.f;
        if (RS) {
            rsA = RS_RECIP ? __fdividef(1.f, RS[rA]) : RS[rA];
            rsB = RS_RECIP ? __fdividef(1.f, RS[rB]) : RS[rB];
        }
        float sumA = 0.f, sumB = 0.f;
#pragma unroll
        for (int ni = 0; ni < 8; ni++) {
            const int col = n0 + nw + ni * 8 + rid * 2;
            float bn0 = 0.f, bn1 = 0.f;
            if (biasN) { bn0 = biasN[col]; bn1 = biasN[col + 1]; }
            float2 v0, v1;
            v0.x = d[mi][ni][0] * alpha + bmA + bn0;
            v0.y = d[mi][ni][1] * alpha + bmA + bn1;
            v1.x = d[mi][ni][2] * alpha + bmB + bn0;
            v1.y = d[mi][ni][3] * alpha + bmB + bn1;
            if (RS) {
                v0.x *= rsA; v0.y *= rsA;
                v1.x *= rsB; v1.y *= rsB;
            }
            if (EXP_C) {
                v0.x = __expf(v0.x); v0.y = __expf(v0.y);
                v1.x = __expf(v1.x); v1.y = __expf(v1.y);
                sumA += v0.x + v0.y;
                sumB += v1.x + v1.y;
            }
            const long o0 = (long)rA * ldc + col;
            const long o1 = (long)rB * ldc + col;
            if (HALF_C) {
                __half* Ch = (__half*)Cv + bz * sC;
                *(__half2*)(Ch + o0) = __floats2half2_rn(v0.x, v0.y);
                *(__half2*)(Ch + o1) = __floats2half2_rn(v1.x, v1.y);
            } else {
                float* Cf = (float*)Cv + bz * sC;
                if (Rb) {
                    float2 ra = *(const float2*)(Rb + o0);
                    float2 rb = *(const float2*)(Rb + o1);
                    v0.x += ra.x; v0.y += ra.y;
                    v1.x += rb.x; v1.y += rb.y;
                }
                *(float2*)(Cf + o0) = v0;
                *(float2*)(Cf + o1) = v1;
            }
        }
        if (EXP_C) {
            // reduce over the 4 rid lanes that share rows rA/rB
            sumA += __shfl_xor_sync(0xffffffffu, sumA, 1);
            sumA += __shfl_xor_sync(0xffffffffu, sumA, 2);
            sumB += __shfl_xor_sync(0xffffffffu, sumB, 1);
            sumB += __shfl_xor_sync(0xffffffffu, sumB, 2);
            if (rid == 0) {
                atomicAdd(RO + rA, sumA);
                atomicAdd(RO + rB, sumB);
            }
        }
    }
}

// ===========================================================================
extern "C" void kernel_launch(void* const* d_in, const int* in_sizes, int n_in,
                              void* d_out, int out_size)
{
    const float* x     = (const float*)d_in[0];
    const float* gamma = (const float*)d_in[1];
    const float* beta  = (const float*)d_in[2];
    const float* wq    = (const float*)d_in[3];
    const float* bq    = (const float*)d_in[4];
    const float* wk    = (const float*)d_in[5];
    const float* bk    = (const float*)d_in[6];
    const float* wv    = (const float*)d_in[7];
    const float* bv    = (const float*)d_in[8];
    const float* wp    = (const float*)d_in[9];
    const float* bp    = (const float*)d_in[10];
    float* out = (float*)d_out;

    __half *pht, *pqk, *pv, *po, *pp, *pw;
    float *pmu, *prs, *pbqk, *prsum;
    cudaGetSymbolAddress((void**)&pht,   g_ht);
    cudaGetSymbolAddress((void**)&pqk,   g_qk);
    cudaGetSymbolAddress((void**)&pv,    g_v);
    cudaGetSymbolAddress((void**)&po,    g_o);
    cudaGetSymbolAddress((void**)&pp,    g_p);
    cudaGetSymbolAddress((void**)&pw,    g_w);
    cudaGetSymbolAddress((void**)&pmu,   g_mu);
    cudaGetSymbolAddress((void**)&prs,   g_rsd);
    cudaGetSymbolAddress((void**)&pbqk,  g_bqk);
    cudaGetSymbolAddress((void**)&prsum, g_rsum);

    cudaFuncSetAttribute((const void*)hgemm<true, false, false>,
                         cudaFuncAttributeMaxDynamicSharedMemorySize, TG_SMEM_BYTES);
    cudaFuncSetAttribute((const void*)hgemm<true, true, false>,
                         cudaFuncAttributeMaxDynamicSharedMemorySize, TG_SMEM_BYTES);
    cudaFuncSetAttribute((const void*)hgemm<true, false, true>,
                         cudaFuncAttributeMaxDynamicSharedMemorySize, TG_SMEM_BYTES);
    cudaFuncSetAttribute((const void*)hgemm<false, false, false>,
                         cudaFuncAttributeMaxDynamicSharedMemorySize, TG_SMEM_BYTES);

    const int WN = CCH * CCH;           // 262144
    __half* rwqk = pw;                  // wq rows 0-511, wk rows 512-1023
    __half* rwv  = pw + 2 * WN;
    __half* rwp  = pw + 3 * WN;

    // 0) convert weights to fp16 + concat q/k biases + zero row sums
    tohalf4_kernel<<<dim3(WN / 1024, 4), 256>>>(wq, wk, wv, wp, pw, WN);
    bcat_kernel<<<4, 256>>>(bq, bk, pbqk);
    cudaMemsetAsync(prsum, 0, BATCH * NSP * sizeof(float));

    // 1) GroupNorm stats
    gn_stats<<<BATCH * GROUPS, 256>>>(x, pmu, prs);

    // 2) fused normalize + transpose -> h_t [N,C] (half)
    dim3 gT(NSP / 32, CCH / 32, BATCH);
    ntrans_kernel<<<gT, 256>>>(x, gamma, beta, pmu, prs, pht);

    // 3) merged q|k: qk[i,o] = sum_c h_t[i,c] wqk[o,c] + bqk[o]
    dim3 gQK(1024 / 128, NSP / 128, BATCH);  // (8, 32, 4)
    hgemm<true, false, false><<<gQK, 128, TG_SMEM_BYTES>>>(
        pht, rwqk, pqk, CCH, CCH, 1024, CN, 0, QKS, 0,
        CCH, 1.f, nullptr, pbqk, nullptr, nullptr, 0, nullptr, 0);

    // 4) v[c,j] = sum_c' wv[c,c'] h_t[j,c'] + bv[c]  (M=CCH, N=NSP)
    dim3 gCN(NSP / 128, CCH / 128, BATCH);   // (32, 4, 4)
    hgemm<true, false, false><<<gCN, 128, TG_SMEM_BYTES>>>(
        rwv, pht, pv, CCH, CCH, NSP, 0, CN, CN, 0,
        CCH, 1.f, bv, nullptr, nullptr, nullptr, 0, nullptr, 0);

    // 5) E[i,j] = exp(scale * q[i]·k[j]) -> half into g_p; row sums via
    //    epilogue atomics into g_rsum (no separate rowsum pass).
    const float scale = 0.04419417382415922f;  // 512^-0.5
    dim3 gSS(NSP / 128, NSP / 128, BATCH);   // (32, 32, 4)
    hgemm<true, true, false><<<gSS, 128, TG_SMEM_BYTES>>>(
        pqk, pqk + 512, pp, 1024, 1024, NSP, QKS, QKS, NNL, 0,
        CCH, scale, nullptr, nullptr, nullptr, nullptr, 0, prsum, NSP);

    // 6) O_t[i,c] = (sum_j E[i,j] v[c,j]) / rsum[i]  (M=NSP, N=CCH, K=NSP)
    dim3 gNC(CCH / 128, NSP / 128, BATCH);   // (4, 32, 4)
    hgemm<true, false, true><<<gNC, 128, TG_SMEM_BYTES>>>(
        pp, pv, po, NSP, NSP, CCH, NNL, CN, CN, 0,
        NSP, 1.f, nullptr, nullptr, nullptr, prsum, NSP, nullptr, 0);

    // 7) out[o,n] = sum_c wp[o,c] O_t[n,c] + bp[o] + x[o,n]  (M=CCH, N=NSP)
    hgemm<false, false, false><<<gCN, 128, TG_SMEM_BYTES>>>(
        rwp, po, out, CCH, CCH, NSP, 0, CN, CN, CN,
        CCH, 1.f, bp, nullptr, x, nullptr, 0, nullptr, 0);
}